// round 7
// baseline (speedup 1.0000x reference)
#include <cuda_runtime.h>
#include <cuda_bf16.h>

// ---------------- problem constants / scratch capacities ----------------
#define MAXB 8
#define MAXN 200000
#define KPRE 512
#define GCAP 2048
#define MAXDET 300
#define NBIN 65536
#define HCOPY 8
#define SCORE_THR 0.05f
#define IOU_THR 0.5f

// ---------------- device scratch (static zero-init; consumers restore zeros) ----------------
__device__ float               d_score[MAXB * MAXN];
__device__ int                 d_label[MAXB * MAXN];
__device__ unsigned int        d_hist1[MAXB * HCOPY * NBIN];   // privatized copies (zeroed by reduceHistK)
__device__ unsigned int        d_hist1s[MAXB * NBIN];          // summed (overwritten every run)
__device__ int                 d_b1[MAXB];
__device__ int                 d_rem[MAXB];
__device__ unsigned int        d_T[MAXB];

// ---------------- K1 (fast, C==80): 4 threads/row, coalesced (R3-proven, unchanged) ----------------
__global__ void scoreK80(const float* __restrict__ cls, int N) {
    int t   = blockIdx.x * blockDim.x + threadIdx.x;
    int row = t >> 2;
    int sub = t & 3;
    int b   = blockIdx.y;
    bool valid = row < N;
    int rclamp = valid ? row : (N - 1);
    const float4* r4 = (const float4*)(cls + ((size_t)b * N + rclamp) * 80);

    float best = -1e30f; int bi = 0;
    #pragma unroll
    for (int k = 0; k < 5; k++) {
        float4 v = r4[sub + 4 * k];
        int e = (sub + 4 * k) * 4;
        if (v.x > best) { best = v.x; bi = e;     }
        if (v.y > best) { best = v.y; bi = e + 1; }
        if (v.z > best) { best = v.z; bi = e + 2; }
        if (v.w > best) { best = v.w; bi = e + 3; }
    }
    #pragma unroll
    for (int off = 2; off >= 1; off >>= 1) {
        float ov = __shfl_down_sync(0xFFFFFFFFu, best, off);
        int   oi = __shfl_down_sync(0xFFFFFFFFu, bi,   off);
        if (ov > best || (ov == best && oi < bi)) { best = ov; bi = oi; }
    }
    if (sub == 0 && valid) {
        size_t base = (size_t)b * N + row;
        d_score[base] = best;
        d_label[base] = bi;
        if (best > SCORE_THR) {
            int copy = blockIdx.x & (HCOPY - 1);
            atomicAdd(&d_hist1[(((b * HCOPY) + copy) << 16) + (__float_as_uint(best) >> 16)], 1u);
        }
    }
}

// ---------------- K1 (generic fallback) ----------------
__global__ void scoreKgen(const float* __restrict__ cls, int N, int C) {
    int b = blockIdx.y;
    int n = blockIdx.x * blockDim.x + threadIdx.x;
    if (n >= N) return;
    size_t base = (size_t)b * N + n;
    const float* row = cls + base * C;
    float best = row[0]; int bi = 0;
    for (int k = 1; k < C; k++) { float v = row[k]; if (v > best) { best = v; bi = k; } }
    d_score[base] = best;
    d_label[base] = bi;
    if (best > SCORE_THR) {
        int copy = blockIdx.x & (HCOPY - 1);
        atomicAdd(&d_hist1[(((b * HCOPY) + copy) << 16) + (__float_as_uint(best) >> 16)], 1u);
    }
}

// ---------------- K1b: sum privatized copies (uint4) AND zero them for the next run ----------------
__global__ void reduceHistK() {
    int q = blockIdx.x * blockDim.x + threadIdx.x;       // over MAXB * NBIN / 4 uint4 groups
    const int PER_B = NBIN / 4;
    if (q >= MAXB * PER_B) return;
    int b = q / PER_B;
    int g = q - b * PER_B;
    uint4 s = make_uint4(0u, 0u, 0u, 0u);
    const uint4 z = make_uint4(0u, 0u, 0u, 0u);
    #pragma unroll
    for (int c = 0; c < HCOPY; c++) {
        uint4* p = (uint4*)&d_hist1[((b * HCOPY + c) << 16)] + g;
        uint4 v = *p;
        s.x += v.x; s.y += v.y; s.z += v.z; s.w += v.w;
        *p = z;                                          // restore zeros for next graph replay
    }
    ((uint4*)d_hist1s)[q] = s;
}

// ---------------- K2: pick level-1 bin containing the 512th score (hierarchical suffix scan) ----
__global__ __launch_bounds__(1024, 1) void selectBin1K() {
    __shared__ unsigned cs[256];
    __shared__ unsigned bs[256];
    __shared__ int s_chunk, s_bin;
    __shared__ unsigned s_above1, s_above2;

    int b   = blockIdx.x;
    int tid = threadIdx.x;
    int w   = tid >> 5, l = tid & 31;
    const unsigned* H = d_hist1s + b * NBIN;
    const int target = KPRE;

    if (tid == 0) { s_chunk = -1; s_bin = 0; s_above1 = 0; s_above2 = 0; }

    #pragma unroll
    for (int cc = 0; cc < 8; cc++) {
        int c = w * 8 + cc;
        const uint4* p = (const uint4*)(H + c * 256);
        uint4 v0 = p[l];
        uint4 v1 = p[l + 32];
        unsigned s = v0.x + v0.y + v0.z + v0.w + v1.x + v1.y + v1.z + v1.w;
        #pragma unroll
        for (int off = 16; off >= 1; off >>= 1)
            s += __shfl_down_sync(0xFFFFFFFFu, s, off);
        if (l == 0) cs[c] = s;
    }
    __syncthreads();

    #pragma unroll
    for (int off = 1; off < 256; off <<= 1) {
        unsigned v = 0, a = 0;
        if (tid < 256) { v = cs[tid]; a = (tid + off < 256) ? cs[tid + off] : 0u; }
        __syncthreads();
        if (tid < 256) cs[tid] = v + a;
        __syncthreads();
    }
    if (tid < 256) {
        unsigned sfx = cs[tid];
        unsigned nxt = (tid == 255) ? 0u : cs[tid + 1];
        if (sfx >= (unsigned)target && nxt < (unsigned)target) { s_chunk = tid; s_above1 = nxt; }
    }
    __syncthreads();

    int c = s_chunk;
    if (c < 0) {
        if (tid == 0) { d_b1[b] = -1; d_rem[b] = 0; }
        return;
    }
    int target2 = target - (int)s_above1;

    if (tid < 256) bs[tid] = H[c * 256 + tid];
    __syncthreads();
    #pragma unroll
    for (int off = 1; off < 256; off <<= 1) {
        unsigned v = 0, a = 0;
        if (tid < 256) { v = bs[tid]; a = (tid + off < 256) ? bs[tid + off] : 0u; }
        __syncthreads();
        if (tid < 256) bs[tid] = v + a;
        __syncthreads();
    }
    if (tid < 256) {
        unsigned sfx = bs[tid];
        unsigned nxt = (tid == 255) ? 0u : bs[tid + 1];
        if (sfx >= (unsigned)target2 && nxt < (unsigned)target2) { s_bin = tid; s_above2 = nxt; }
    }
    __syncthreads();

    if (tid == 0) {
        d_b1[b]  = c * 256 + s_bin;
        d_rem[b] = target2 - (int)s_above2;
    }
}

// ---------------- K3 (NEW): per-image smem 12-bit sub-histogram -> 28-bit threshold key ----------
__global__ __launch_bounds__(1024, 1) void thresholdK(int N) {
    __shared__ unsigned hist[4096];
    __shared__ unsigned cs[256];
    __shared__ int s_chunk; __shared__ unsigned s_above;

    int b = blockIdx.x, tid = threadIdx.x;
    int b1 = d_b1[b];
    if (b1 < 0) { if (tid == 0) d_T[b] = 1u; return; }

    for (int i = tid; i < 4096; i += 1024) hist[i] = 0u;
    if (tid == 0) { s_chunk = -1; s_above = 0; }
    __syncthreads();

    const float* S = d_score + (size_t)b * N;
    int N4 = N >> 2;
    for (int q = tid; q < N4; q += 1024) {
        float4 v = ((const float4*)S)[q];
        float vv[4] = {v.x, v.y, v.z, v.w};
        #pragma unroll
        for (int k = 0; k < 4; k++) {
            if (vv[k] > SCORE_THR) {
                unsigned key = __float_as_uint(vv[k]);
                if ((int)(key >> 16) == b1)
                    atomicAdd(&hist[(key >> 4) & 0xFFFu], 1u);
            }
        }
    }
    for (int n = (N4 << 2) + tid; n < N; n += 1024) {
        float s = S[n];
        if (s > SCORE_THR) {
            unsigned key = __float_as_uint(s);
            if ((int)(key >> 16) == b1)
                atomicAdd(&hist[(key >> 4) & 0xFFFu], 1u);
        }
    }
    __syncthreads();

    int target = d_rem[b];

    // 256 chunks of 16 sub-bins
    if (tid < 256) {
        unsigned s = 0;
        #pragma unroll
        for (int j = 0; j < 16; j++) s += hist[tid * 16 + j];
        cs[tid] = s;
    }
    __syncthreads();
    #pragma unroll
    for (int off = 1; off < 256; off <<= 1) {
        unsigned v = 0, a = 0;
        if (tid < 256) { v = cs[tid]; a = (tid + off < 256) ? cs[tid + off] : 0u; }
        __syncthreads();
        if (tid < 256) cs[tid] = v + a;
        __syncthreads();
    }
    if (tid < 256) {
        unsigned sfx = cs[tid];
        unsigned nxt = (tid == 255) ? 0u : cs[tid + 1];
        if (sfx >= (unsigned)target && nxt < (unsigned)target) { s_chunk = tid; s_above = nxt; }
    }
    __syncthreads();

    if (tid == 0) {
        int c = s_chunk;
        if (c < 0) {
            d_T[b] = ((unsigned)b1) << 16;           // fallback: whole bin
        } else {
            int target2 = target - (int)s_above;
            unsigned cum = 0; int bin = 0;
            for (int j = 15; j >= 0; j--) {
                cum += hist[c * 16 + j];
                if ((int)cum >= target2) { bin = j; break; }
            }
            d_T[b] = (((unsigned)b1) << 16) | (unsigned)((c * 16 + bin) << 4);
        }
    }
}

// ---------------- K4 (NEW): gather into smem + sort + decode + NMS + output ----------------
__global__ __launch_bounds__(1024, 1) void gatherFinalizeK(
    const float* __restrict__ anchors, const float* __restrict__ regs,
    const float* __restrict__ sizes, float* __restrict__ out, int N, int B)
{
    int b = blockIdx.x;
    int tid = threadIdx.x;

    __shared__ __align__(16) unsigned char sm[47296];
    __shared__ int sCnt;
    unsigned int*       mask  = (unsigned int*)sm;            // [512][16]
    unsigned long long* arr   = (unsigned long long*)sm;      // [2048]
    float4*             sBox  = (float4*)(sm + 32768);
    float*              sArea = (float*) (sm + 40960);
    float*              sScore= (float*) (sm + 43008);
    int*                sLabel= (int*)   (sm + 45056);
    unsigned int*       keepW = (unsigned int*)(sm + 47104);
    int*                warpCnt = (int*)(sm + 47168);

    if (tid == 0) sCnt = 0;
    __syncthreads();

    // ---- gather survivors straight into the smem sort buffer ----
    unsigned T = d_T[b];
    const float* SC = d_score + (size_t)b * N;
    int N4 = N >> 2;
    for (int q = tid; q < N4; q += 1024) {
        float4 v = ((const float4*)SC)[q];
        float vv[4] = {v.x, v.y, v.z, v.w};
        int n0 = q << 2;
        #pragma unroll
        for (int k = 0; k < 4; k++) {
            if (vv[k] > SCORE_THR) {
                unsigned key = __float_as_uint(vv[k]);
                if (key >= T) {
                    int p = atomicAdd(&sCnt, 1);
                    if (p < GCAP)
                        arr[p] = ((unsigned long long)key << 32) | (unsigned)(~(unsigned)(n0 + k));
                }
            }
        }
    }
    for (int n = (N4 << 2) + tid; n < N; n += 1024) {
        float s = SC[n];
        if (s > SCORE_THR) {
            unsigned key = __float_as_uint(s);
            if (key >= T) {
                int p = atomicAdd(&sCnt, 1);
                if (p < GCAP)
                    arr[p] = ((unsigned long long)key << 32) | (unsigned)(~(unsigned)n);
            }
        }
    }
    __syncthreads();

    int cnt = sCnt; if (cnt > GCAP) cnt = GCAP;
    int nv  = cnt < KPRE ? cnt : KPRE;
    int S   = (cnt <= 512) ? 512 : ((cnt <= 1024) ? 1024 : 2048);

    for (int i = cnt + tid; i < S; i += 1024) arr[i] = 0ull;
    __syncthreads();

    // ---- bitonic sort, S elems descending (key desc, idx asc) ----
    for (int k = 2; k <= S; k <<= 1) {
        for (int j = k >> 1; j >= 1; j >>= 1) {
            if (tid < (S >> 1)) {
                int i = ((tid & ~(j - 1)) << 1) | (tid & (j - 1));
                int p = i + j;
                bool up = (i & k) != 0;
                unsigned long long a = arr[i], c2 = arr[p];
                bool sw = up ? (a > c2) : (a < c2);
                if (sw) { arr[i] = c2; arr[p] = a; }
            }
            __syncthreads();
        }
    }

    // ---- decode + clip boxes for top nv; default-fill output with -1 ----
    float H = sizes[b * 2 + 0], W = sizes[b * 2 + 1];
    if (tid < nv) {
        unsigned long long v = arr[tid];
        unsigned key = (unsigned)(v >> 32);
        int idx = (int)(~(unsigned)v);
        size_t off = (size_t)b * N + idx;
        float4 a = ((const float4*)anchors)[off];
        float4 r = ((const float4*)regs)[off];
        float w = a.z - a.x, h = a.w - a.y;
        float cx = a.x + 0.5f * w, cy = a.y + 0.5f * h;
        float dx = r.x * 0.1f, dy = r.y * 0.1f, dw = r.z * 0.2f, dh = r.w * 0.2f;
        float pcx = cx + dx * w, pcy = cy + dy * h;
        float pw = expf(dw) * w, ph = expf(dh) * h;
        float x1 = pcx - 0.5f * pw, y1 = pcy - 0.5f * ph;
        float x2 = pcx + 0.5f * pw, y2 = pcy + 0.5f * ph;
        x1 = fminf(fmaxf(x1, 0.f), W); x2 = fminf(fmaxf(x2, 0.f), W);
        y1 = fminf(fmaxf(y1, 0.f), H); y2 = fminf(fmaxf(y2, 0.f), H);
        sBox[tid]  = make_float4(x1, y1, x2, y2);
        sArea[tid] = (x2 - x1) * (y2 - y1);
        sScore[tid]= __uint_as_float(key);
        sLabel[tid]= d_label[off];
    }
    float* outB = out;
    float* outS = out + (size_t)B * MAXDET * 4;
    float* outL = out + (size_t)B * MAXDET * 5;
    if (tid < MAXDET) {
        ((float4*)outB)[b * MAXDET + tid] = make_float4(-1.f, -1.f, -1.f, -1.f);
        outS[b * MAXDET + tid] = -1.f;
        outL[b * MAXDET + tid] = -1.f;
    }
    __syncthreads();   // arr reads done -> mask may now overwrite that region

    // ---- parallel IoU suppression bitmask (division-free) ----
    if (tid < KPRE) {
        float4 bi; float ai = 0.f;
        bool v = tid < nv;
        if (v) { bi = sBox[tid]; ai = sArea[tid]; }
        for (int w = 0; w < 16; w++) {
            unsigned word = 0;
            if (v) {
                int j0 = w * 32, j1 = j0 + 32;
                if (j1 > nv) j1 = nv;
                int js = (tid + 1 > j0) ? tid + 1 : j0;
                for (int j = js; j < j1; j++) {
                    float4 bj = sBox[j];
                    float lx = fmaxf(bi.x, bj.x), ly = fmaxf(bi.y, bj.y);
                    float rx = fminf(bi.z, bj.z), ry = fminf(bi.w, bj.w);
                    float iw = fmaxf(rx - lx, 0.f), ih = fmaxf(ry - ly, 0.f);
                    float inter = iw * ih;
                    float lhs = inter * (1.0f + IOU_THR);
                    float rhs = IOU_THR * (ai + sArea[j] + 1e-9f);
                    if (lhs > rhs) word |= 1u << (j & 31);
                }
            }
            mask[tid * 16 + w] = word;
        }
    }
    __syncthreads();

    // ---- warp-serial greedy resolution; iterate only KEPT candidates via ffs ----
    if (tid < 32) {
        unsigned kw = 0;
        if (tid < 16) {
            int full = nv >> 5, rem = nv & 31;
            kw = (tid < full) ? 0xFFFFFFFFu
               : ((tid == full && rem) ? ((1u << rem) - 1u) : 0u);
        }
        for (int g = 0; g < 16; g++) {
            unsigned ow = __shfl_sync(0xFFFFFFFFu, kw, g);
            while (ow) {
                int bit = __ffs(ow) - 1;
                int i = g * 32 + bit;
                if (tid < 16) kw &= ~mask[i * 16 + tid];
                ow = __shfl_sync(0xFFFFFFFFu, kw, g);
                ow &= (bit == 31) ? 0u : ~((2u << bit) - 1u);
            }
        }
        if (tid < 16) keepW[tid] = kw;
    }
    __syncthreads();

    // ---- compact kept candidates (score order) into first <=300 slots ----
    bool kept = false;
    if (tid < nv) kept = (keepW[tid >> 5] >> (tid & 31)) & 1u;
    unsigned wm = __ballot_sync(0xFFFFFFFFu, kept);
    int w = tid >> 5, lane = tid & 31;
    if (lane == 0) warpCnt[w] = __popc(wm);
    __syncthreads();
    if (kept) {
        int prefix = 0;
        for (int i = 0; i < w; i++) prefix += warpCnt[i];
        int pos = prefix + __popc(wm & ((1u << lane) - 1u));
        if (pos < MAXDET) {
            ((float4*)outB)[b * MAXDET + pos] = sBox[tid];
            outS[b * MAXDET + pos] = sScore[tid];
            outL[b * MAXDET + pos] = (float)sLabel[tid];
        }
    }
}

// ---------------- launch ----------------
extern "C" void kernel_launch(void* const* d_in, const int* in_sizes, int n_in,
                              void* d_out, int out_size) {
    const float* anchors = (const float*)d_in[0];
    const float* regs    = (const float*)d_in[1];
    const float* cls     = (const float*)d_in[2];
    const float* sizes   = (const float*)d_in[3];

    int B = in_sizes[3] / 2;            // sizes is [B,2]
    if (B <= 0 || B > MAXB) B = MAXB;
    int N = in_sizes[0] / (B * 4);      // anchors [B,N,4]
    long long clsElems = (long long)in_sizes[2];
    int C = (int)(clsElems / ((long long)B * N));

    if (C == 80) {
        dim3 gridS(((N * 4) + 255) / 256, B);
        scoreK80<<<gridS, 256>>>(cls, N);
    } else {
        dim3 gridBN((N + 255) / 256, B);
        scoreKgen<<<gridBN, 256>>>(cls, N, C);
    }
    reduceHistK<<<(MAXB * (NBIN / 4) + 255) / 256, 256>>>();
    selectBin1K<<<B, 1024>>>();
    thresholdK<<<B, 1024>>>(N);
    gatherFinalizeK<<<B, 1024>>>(anchors, regs, sizes, (float*)d_out, N, B);
}

// round 8
// speedup vs baseline: 1.0866x; 1.0866x over previous
#include <cuda_runtime.h>
#include <cuda_bf16.h>

// ---------------- problem constants / scratch capacities ----------------
#define MAXB 8
#define MAXN 200000
#define KPRE 512
#define GCAP 2048
#define MAXDET 300
#define NBIN 65536
#define HCOPY 8
#define SCORE_THR 0.05f
#define IOU_THR 0.5f

// ---------------- device scratch (static zero-init; kernels restore zeros) ----------------
__device__ float               d_score[MAXB * MAXN];
__device__ int                 d_label[MAXB * MAXN];
__device__ unsigned int        d_hist1[MAXB * HCOPY * NBIN];   // zeroed by reduceHistK after use
__device__ unsigned int        d_hist1s[MAXB * NBIN];          // overwritten every run
__device__ unsigned int        d_hist2[MAXB * NBIN];           // zeroed by gatherK after use
__device__ int                 d_b1[MAXB];
__device__ int                 d_rem[MAXB];
__device__ unsigned int        d_T[MAXB];
__device__ unsigned long long  d_gath[MAXB * GCAP];            // only first d_cnt[b] entries read
__device__ int                 d_cnt[MAXB];                    // reset by finalizeK after use

// ---------------- K1 (fast, C==80): 4 threads/row, coalesced (proven) ----------------
__global__ void scoreK80(const float* __restrict__ cls, int N) {
    int t   = blockIdx.x * blockDim.x + threadIdx.x;
    int row = t >> 2;
    int sub = t & 3;
    int b   = blockIdx.y;
    bool valid = row < N;
    int rclamp = valid ? row : (N - 1);
    const float4* r4 = (const float4*)(cls + ((size_t)b * N + rclamp) * 80);

    float best = -1e30f; int bi = 0;
    #pragma unroll
    for (int k = 0; k < 5; k++) {
        float4 v = r4[sub + 4 * k];
        int e = (sub + 4 * k) * 4;
        if (v.x > best) { best = v.x; bi = e;     }
        if (v.y > best) { best = v.y; bi = e + 1; }
        if (v.z > best) { best = v.z; bi = e + 2; }
        if (v.w > best) { best = v.w; bi = e + 3; }
    }
    #pragma unroll
    for (int off = 2; off >= 1; off >>= 1) {
        float ov = __shfl_down_sync(0xFFFFFFFFu, best, off);
        int   oi = __shfl_down_sync(0xFFFFFFFFu, bi,   off);
        if (ov > best || (ov == best && oi < bi)) { best = ov; bi = oi; }
    }
    if (sub == 0 && valid) {
        size_t base = (size_t)b * N + row;
        d_score[base] = best;
        d_label[base] = bi;
        if (best > SCORE_THR) {
            int copy = blockIdx.x & (HCOPY - 1);
            atomicAdd(&d_hist1[(((b * HCOPY) + copy) << 16) + (__float_as_uint(best) >> 16)], 1u);
        }
    }
}

// ---------------- K1 (generic fallback) ----------------
__global__ void scoreKgen(const float* __restrict__ cls, int N, int C) {
    int b = blockIdx.y;
    int n = blockIdx.x * blockDim.x + threadIdx.x;
    if (n >= N) return;
    size_t base = (size_t)b * N + n;
    const float* row = cls + base * C;
    float best = row[0]; int bi = 0;
    for (int k = 1; k < C; k++) { float v = row[k]; if (v > best) { best = v; bi = k; } }
    d_score[base] = best;
    d_label[base] = bi;
    if (best > SCORE_THR) {
        int copy = blockIdx.x & (HCOPY - 1);
        atomicAdd(&d_hist1[(((b * HCOPY) + copy) << 16) + (__float_as_uint(best) >> 16)], 1u);
    }
}

// ---------------- K1b: sum privatized copies (uint4) AND zero them for next replay ----------------
__global__ void reduceHistK() {
    int q = blockIdx.x * blockDim.x + threadIdx.x;       // over MAXB * NBIN/4 uint4 groups
    const int PER_B = NBIN / 4;
    if (q >= MAXB * PER_B) return;
    int b = q / PER_B;
    int g = q - b * PER_B;
    uint4 s = make_uint4(0u, 0u, 0u, 0u);
    const uint4 z = make_uint4(0u, 0u, 0u, 0u);
    #pragma unroll
    for (int c = 0; c < HCOPY; c++) {
        uint4* p = (uint4*)&d_hist1[((b * HCOPY + c) << 16)] + g;
        uint4 v = *p;
        s.x += v.x; s.y += v.y; s.z += v.z; s.w += v.w;
        *p = z;
    }
    ((uint4*)d_hist1s)[q] = s;
}

// ---------------- bin selection: hierarchical suffix scan, 1024 thr/batch ----
// LEVEL 1: H = d_hist1s, target = KPRE     -> d_b1, d_rem
// LEVEL 2: H = d_hist2,  target = d_rem[b] -> d_T
template <int LEVEL>
__global__ __launch_bounds__(1024, 1) void selectBinK() {
    __shared__ unsigned cs[256];
    __shared__ unsigned bs[256];
    __shared__ int s_chunk, s_bin;
    __shared__ unsigned s_above1, s_above2;

    int b   = blockIdx.x;
    int tid = threadIdx.x;
    int w   = tid >> 5, l = tid & 31;

    int target;
    const unsigned* H;
    if (LEVEL == 1) {
        target = KPRE;
        H = d_hist1s + b * NBIN;
    } else {
        if (d_b1[b] < 0) { if (tid == 0) d_T[b] = 1u; return; }
        target = d_rem[b];
        H = d_hist2 + b * NBIN;
    }
    if (tid == 0) { s_chunk = -1; s_bin = 0; s_above1 = 0; s_above2 = 0; }

    #pragma unroll
    for (int cc = 0; cc < 8; cc++) {
        int c = w * 8 + cc;
        const uint4* p = (const uint4*)(H + c * 256);
        uint4 v0 = p[l];
        uint4 v1 = p[l + 32];
        unsigned s = v0.x + v0.y + v0.z + v0.w + v1.x + v1.y + v1.z + v1.w;
        #pragma unroll
        for (int off = 16; off >= 1; off >>= 1)
            s += __shfl_down_sync(0xFFFFFFFFu, s, off);
        if (l == 0) cs[c] = s;
    }
    __syncthreads();

    #pragma unroll
    for (int off = 1; off < 256; off <<= 1) {
        unsigned v = 0, a = 0;
        if (tid < 256) { v = cs[tid]; a = (tid + off < 256) ? cs[tid + off] : 0u; }
        __syncthreads();
        if (tid < 256) cs[tid] = v + a;
        __syncthreads();
    }
    if (tid < 256) {
        unsigned sfx = cs[tid];
        unsigned nxt = (tid == 255) ? 0u : cs[tid + 1];
        if (sfx >= (unsigned)target && nxt < (unsigned)target) { s_chunk = tid; s_above1 = nxt; }
    }
    __syncthreads();

    int c = s_chunk;
    if (c < 0) {
        if (tid == 0) {
            if (LEVEL == 1) { d_b1[b] = -1; d_rem[b] = 0; }
            else            { d_T[b] = 1u; }
        }
        return;
    }
    int target2 = target - (int)s_above1;

    if (tid < 256) bs[tid] = H[c * 256 + tid];
    __syncthreads();
    #pragma unroll
    for (int off = 1; off < 256; off <<= 1) {
        unsigned v = 0, a = 0;
        if (tid < 256) { v = bs[tid]; a = (tid + off < 256) ? bs[tid + off] : 0u; }
        __syncthreads();
        if (tid < 256) bs[tid] = v + a;
        __syncthreads();
    }
    if (tid < 256) {
        unsigned sfx = bs[tid];
        unsigned nxt = (tid == 255) ? 0u : bs[tid + 1];
        if (sfx >= (unsigned)target2 && nxt < (unsigned)target2) { s_bin = tid; s_above2 = nxt; }
    }
    __syncthreads();

    if (tid == 0) {
        int bin = c * 256 + s_bin;
        if (LEVEL == 1) {
            d_b1[b]  = bin;
            d_rem[b] = target2 - (int)s_above2;
        } else {
            d_T[b] = (((unsigned)d_b1[b]) << 16) | (unsigned)bin;
        }
    }
}

// ---------------- K3: level-2 histogram (vectorized scan, full-chip) ----------------
__global__ void hist2K(int N) {
    int b  = blockIdx.y;
    int q  = blockIdx.x * blockDim.x + threadIdx.x;
    int n0 = q * 4;
    if (n0 >= N) return;
    int b1 = d_b1[b];
    if (b1 < 0) return;
    const float* S = d_score + (size_t)b * N;
    if (n0 + 3 < N) {
        float4 v = *(const float4*)(S + n0);
        float vv[4] = {v.x, v.y, v.z, v.w};
        #pragma unroll
        for (int k = 0; k < 4; k++) {
            if (vv[k] > SCORE_THR) {
                unsigned key = __float_as_uint(vv[k]);
                if ((int)(key >> 16) == b1)
                    atomicAdd(&d_hist2[(b << 16) + (key & 0xFFFFu)], 1u);
            }
        }
    } else {
        for (int k = 0; k < 4 && n0 + k < N; k++) {
            float s = S[n0 + k];
            if (s > SCORE_THR) {
                unsigned key = __float_as_uint(s);
                if ((int)(key >> 16) == b1)
                    atomicAdd(&d_hist2[(b << 16) + (key & 0xFFFFu)], 1u);
            }
        }
    }
}

// ---------------- K5: gather candidates with key >= T; also zero d_hist2 for next replay ----------
__global__ void gatherK(int N, int gx) {
    int b  = blockIdx.y;
    int q  = blockIdx.x * blockDim.x + threadIdx.x;
    int n0 = q * 4;

    // grid-stride zero of d_hist2 (runs AFTER selectBin2 read it; ready for next replay)
    {
        int flat = (b * gx + blockIdx.x) * blockDim.x + threadIdx.x;
        int total = gx * MAXB * blockDim.x;
        for (int i = flat; i < MAXB * NBIN; i += total) d_hist2[i] = 0u;
    }

    if (n0 >= N) return;
    unsigned T = d_T[b];
    const float* S = d_score + (size_t)b * N;
    if (n0 + 3 < N) {
        float4 v = *(const float4*)(S + n0);
        float vv[4] = {v.x, v.y, v.z, v.w};
        #pragma unroll
        for (int k = 0; k < 4; k++) {
            if (vv[k] > SCORE_THR) {
                unsigned key = __float_as_uint(vv[k]);
                if (key >= T) {
                    int p = atomicAdd(&d_cnt[b], 1);
                    if (p < GCAP)
                        d_gath[b * GCAP + p] =
                            ((unsigned long long)key << 32) | (unsigned)(~(unsigned)(n0 + k));
                }
            }
        }
    } else {
        for (int k = 0; k < 4 && n0 + k < N; k++) {
            float s = S[n0 + k];
            if (s > SCORE_THR) {
                unsigned key = __float_as_uint(s);
                if (key >= T) {
                    int p = atomicAdd(&d_cnt[b], 1);
                    if (p < GCAP)
                        d_gath[b * GCAP + p] =
                            ((unsigned long long)key << 32) | (unsigned)(~(unsigned)(n0 + k));
                }
            }
        }
    }
}

// ---------------- K6: sort candidates, decode+clip boxes, NMS, write output ----------------
__global__ __launch_bounds__(1024, 1) void finalizeK(
    const float* __restrict__ anchors, const float* __restrict__ regs,
    const float* __restrict__ sizes, float* __restrict__ out, int N, int B)
{
    int b = blockIdx.x;
    int tid = threadIdx.x;

    __shared__ __align__(16) unsigned char sm[47296];
    unsigned int*       mask  = (unsigned int*)sm;            // [512][16]
    unsigned long long* arr   = (unsigned long long*)sm;      // [2048]
    float4*             sBox  = (float4*)(sm + 32768);
    float*              sArea = (float*) (sm + 40960);
    float*              sScore= (float*) (sm + 43008);
    int*                sLabel= (int*)   (sm + 45056);
    unsigned int*       keepW = (unsigned int*)(sm + 47104);
    int*                warpCnt = (int*)(sm + 47168);

    int cnt = d_cnt[b]; if (cnt > GCAP) cnt = GCAP;
    int nv  = cnt < KPRE ? cnt : KPRE;
    int S   = (cnt <= 512) ? 512 : ((cnt <= 1024) ? 1024 : 2048);

    for (int i = tid; i < S; i += blockDim.x)
        arr[i] = (i < cnt) ? d_gath[b * GCAP + i] : 0ull;
    __syncthreads();
    if (tid == 0) d_cnt[b] = 0;     // reset for next graph replay (after read)

    // bitonic sort, S elems descending (key desc, idx asc)
    for (int k = 2; k <= S; k <<= 1) {
        for (int j = k >> 1; j >= 1; j >>= 1) {
            if (tid < (S >> 1)) {
                int i = ((tid & ~(j - 1)) << 1) | (tid & (j - 1));
                int p = i + j;
                bool up = (i & k) != 0;
                unsigned long long a = arr[i], c2 = arr[p];
                bool sw = up ? (a > c2) : (a < c2);
                if (sw) { arr[i] = c2; arr[p] = a; }
            }
            __syncthreads();
        }
    }

    // decode + clip boxes for top nv; default-fill output with -1
    float H = sizes[b * 2 + 0], W = sizes[b * 2 + 1];
    if (tid < nv) {
        unsigned long long v = arr[tid];
        unsigned key = (unsigned)(v >> 32);
        int idx = (int)(~(unsigned)v);
        size_t off = (size_t)b * N + idx;
        float4 a = ((const float4*)anchors)[off];
        float4 r = ((const float4*)regs)[off];
        float w = a.z - a.x, h = a.w - a.y;
        float cx = a.x + 0.5f * w, cy = a.y + 0.5f * h;
        float dx = r.x * 0.1f, dy = r.y * 0.1f, dw = r.z * 0.2f, dh = r.w * 0.2f;
        float pcx = cx + dx * w, pcy = cy + dy * h;
        float pw = expf(dw) * w, ph = expf(dh) * h;
        float x1 = pcx - 0.5f * pw, y1 = pcy - 0.5f * ph;
        float x2 = pcx + 0.5f * pw, y2 = pcy + 0.5f * ph;
        x1 = fminf(fmaxf(x1, 0.f), W); x2 = fminf(fmaxf(x2, 0.f), W);
        y1 = fminf(fmaxf(y1, 0.f), H); y2 = fminf(fmaxf(y2, 0.f), H);
        sBox[tid]  = make_float4(x1, y1, x2, y2);
        sArea[tid] = (x2 - x1) * (y2 - y1);
        sScore[tid]= __uint_as_float(key);
        sLabel[tid]= d_label[off];
    }
    float* outB = out;
    float* outS = out + (size_t)B * MAXDET * 4;
    float* outL = out + (size_t)B * MAXDET * 5;
    if (tid < MAXDET) {
        ((float4*)outB)[b * MAXDET + tid] = make_float4(-1.f, -1.f, -1.f, -1.f);
        outS[b * MAXDET + tid] = -1.f;
        outL[b * MAXDET + tid] = -1.f;
    }
    __syncthreads();   // arr reads done -> mask may now overwrite that region

    // parallel IoU suppression bitmask (division-free)
    if (tid < KPRE) {
        float4 bi; float ai = 0.f;
        bool v = tid < nv;
        if (v) { bi = sBox[tid]; ai = sArea[tid]; }
        for (int w = 0; w < 16; w++) {
            unsigned word = 0;
            if (v) {
                int j0 = w * 32, j1 = j0 + 32;
                if (j1 > nv) j1 = nv;
                int js = (tid + 1 > j0) ? tid + 1 : j0;
                for (int j = js; j < j1; j++) {
                    float4 bj = sBox[j];
                    float lx = fmaxf(bi.x, bj.x), ly = fmaxf(bi.y, bj.y);
                    float rx = fminf(bi.z, bj.z), ry = fminf(bi.w, bj.w);
                    float iw = fmaxf(rx - lx, 0.f), ih = fmaxf(ry - ly, 0.f);
                    float inter = iw * ih;
                    float lhs = inter * (1.0f + IOU_THR);
                    float rhs = IOU_THR * (ai + sArea[j] + 1e-9f);
                    if (lhs > rhs) word |= 1u << (j & 31);
                }
            }
            mask[tid * 16 + w] = word;
        }
    }
    __syncthreads();

    // warp-serial greedy resolution; iterate only KEPT candidates via ffs
    if (tid < 32) {
        unsigned kw = 0;
        if (tid < 16) {
            int full = nv >> 5, rem = nv & 31;
            kw = (tid < full) ? 0xFFFFFFFFu
               : ((tid == full && rem) ? ((1u << rem) - 1u) : 0u);
        }
        for (int g = 0; g < 16; g++) {
            unsigned ow = __shfl_sync(0xFFFFFFFFu, kw, g);
            while (ow) {
                int bit = __ffs(ow) - 1;
                int i = g * 32 + bit;
                if (tid < 16) kw &= ~mask[i * 16 + tid];
                ow = __shfl_sync(0xFFFFFFFFu, kw, g);
                ow &= (bit == 31) ? 0u : ~((2u << bit) - 1u);
            }
        }
        if (tid < 16) keepW[tid] = kw;
    }
    __syncthreads();

    // compact kept candidates (score order) into first <=300 slots
    bool kept = false;
    if (tid < nv) kept = (keepW[tid >> 5] >> (tid & 31)) & 1u;
    unsigned wm = __ballot_sync(0xFFFFFFFFu, kept);
    int w = tid >> 5, lane = tid & 31;
    if (lane == 0) warpCnt[w] = __popc(wm);
    __syncthreads();
    if (kept) {
        int prefix = 0;
        for (int i = 0; i < w; i++) prefix += warpCnt[i];
        int pos = prefix + __popc(wm & ((1u << lane) - 1u));
        if (pos < MAXDET) {
            ((float4*)outB)[b * MAXDET + pos] = sBox[tid];
            outS[b * MAXDET + pos] = sScore[tid];
            outL[b * MAXDET + pos] = (float)sLabel[tid];
        }
    }
}

// ---------------- launch ----------------
extern "C" void kernel_launch(void* const* d_in, const int* in_sizes, int n_in,
                              void* d_out, int out_size) {
    const float* anchors = (const float*)d_in[0];
    const float* regs    = (const float*)d_in[1];
    const float* cls     = (const float*)d_in[2];
    const float* sizes   = (const float*)d_in[3];

    int B = in_sizes[3] / 2;            // sizes is [B,2]
    if (B <= 0 || B > MAXB) B = MAXB;
    int N = in_sizes[0] / (B * 4);      // anchors [B,N,4]
    long long clsElems = (long long)in_sizes[2];
    int C = (int)(clsElems / ((long long)B * N));

    int N4 = (N + 3) / 4;
    int gx = (N4 + 255) / 256;
    dim3 gridV(gx, B);

    if (C == 80) {
        dim3 gridS(((N * 4) + 255) / 256, B);
        scoreK80<<<gridS, 256>>>(cls, N);
    } else {
        dim3 gridBN((N + 255) / 256, B);
        scoreKgen<<<gridBN, 256>>>(cls, N, C);
    }
    reduceHistK<<<(MAXB * (NBIN / 4) + 255) / 256, 256>>>();
    selectBinK<1><<<B, 1024>>>();
    hist2K<<<gridV, 256>>>(N);
    selectBinK<2><<<B, 1024>>>();
    gatherK<<<gridV, 256>>>(N, gx);
    finalizeK<<<B, 1024>>>(anchors, regs, sizes, (float*)d_out, N, B);
}

// round 9
// speedup vs baseline: 1.1948x; 1.0995x over previous
#include <cuda_runtime.h>
#include <cuda_bf16.h>

// ---------------- problem constants / scratch capacities ----------------
#define MAXB 8
#define MAXN 200000
#define KPRE 512
#define GCAP 2048
#define MAXDET 300
#define NBIN 65536
#define SCORE_THR 0.05f
#define IOU_THR 0.5f
// fine radix bins: bin = (key - KEY_BASE) >> 7, covering [0.5, 1.0) in 128-ULP steps
#define KEY_BASE 0x3F000000u

// ---------------- device scratch (static zero-init; kernels restore zeros) ----------------
__device__ float               d_score[MAXB * MAXN];
__device__ int                 d_label[MAXB * MAXN];
__device__ unsigned int        d_hist[MAXB * NBIN];   // fine histogram; zeroed by gatherK after use
__device__ unsigned int        d_T[MAXB];
__device__ unsigned long long  d_gath[MAXB * GCAP];   // only first d_cnt[b] entries read
__device__ int                 d_cnt[MAXB];           // reset by finalizeK after use

// ---------------- fine-bin helper ----------------
__device__ __forceinline__ int fine_bin(unsigned key) {
    if (key < KEY_BASE) return 0;
    unsigned d = key - KEY_BASE;
    return (d >= (NBIN << 7)) ? (NBIN - 1) : (int)(d >> 7);
}

// ---------------- K1 (fast, C==80): 4 threads/row, coalesced (load path proven) ----------------
__global__ void scoreK80(const float* __restrict__ cls, int N) {
    int t   = blockIdx.x * blockDim.x + threadIdx.x;
    int row = t >> 2;
    int sub = t & 3;
    int b   = blockIdx.y;
    bool valid = row < N;
    int rclamp = valid ? row : (N - 1);
    const float4* r4 = (const float4*)(cls + ((size_t)b * N + rclamp) * 80);

    float best = -1e30f; int bi = 0;
    #pragma unroll
    for (int k = 0; k < 5; k++) {
        float4 v = r4[sub + 4 * k];
        int e = (sub + 4 * k) * 4;
        if (v.x > best) { best = v.x; bi = e;     }
        if (v.y > best) { best = v.y; bi = e + 1; }
        if (v.z > best) { best = v.z; bi = e + 2; }
        if (v.w > best) { best = v.w; bi = e + 3; }
    }
    #pragma unroll
    for (int off = 2; off >= 1; off >>= 1) {
        float ov = __shfl_down_sync(0xFFFFFFFFu, best, off);
        int   oi = __shfl_down_sync(0xFFFFFFFFu, bi,   off);
        if (ov > best || (ov == best && oi < bi)) { best = ov; bi = oi; }
    }
    if (sub == 0 && valid) {
        size_t base = (size_t)b * N + row;
        d_score[base] = best;
        d_label[base] = bi;
        if (best > SCORE_THR) {
            int bin = fine_bin(__float_as_uint(best));
            atomicAdd(&d_hist[(b << 16) + bin], 1u);
        }
    }
}

// ---------------- K1 (generic fallback) ----------------
__global__ void scoreKgen(const float* __restrict__ cls, int N, int C) {
    int b = blockIdx.y;
    int n = blockIdx.x * blockDim.x + threadIdx.x;
    if (n >= N) return;
    size_t base = (size_t)b * N + n;
    const float* row = cls + base * C;
    float best = row[0]; int bi = 0;
    for (int k = 1; k < C; k++) { float v = row[k]; if (v > best) { best = v; bi = k; } }
    d_score[base] = best;
    d_label[base] = bi;
    if (best > SCORE_THR) {
        int bin = fine_bin(__float_as_uint(best));
        atomicAdd(&d_hist[(b << 16) + bin], 1u);
    }
}

// ---------------- K2: single-level fine-bin selection -> exact gather threshold key ----------------
__global__ __launch_bounds__(1024, 1) void selectTK() {
    __shared__ unsigned cs[256];
    __shared__ unsigned bs[256];
    __shared__ int s_chunk, s_bin;
    __shared__ unsigned s_above1;

    int b   = blockIdx.x;
    int tid = threadIdx.x;
    int w   = tid >> 5, l = tid & 31;
    const unsigned* H = d_hist + b * NBIN;
    const int target = KPRE;

    if (tid == 0) { s_chunk = -1; s_bin = 0; s_above1 = 0; }

    // chunk sums (vectorized): warp w covers chunks [8w, 8w+8)
    #pragma unroll
    for (int cc = 0; cc < 8; cc++) {
        int c = w * 8 + cc;
        const uint4* p = (const uint4*)(H + c * 256);
        uint4 v0 = p[l];
        uint4 v1 = p[l + 32];
        unsigned s = v0.x + v0.y + v0.z + v0.w + v1.x + v1.y + v1.z + v1.w;
        #pragma unroll
        for (int off = 16; off >= 1; off >>= 1)
            s += __shfl_down_sync(0xFFFFFFFFu, s, off);
        if (l == 0) cs[c] = s;
    }
    __syncthreads();

    // suffix scan over 256 chunk sums
    #pragma unroll
    for (int off = 1; off < 256; off <<= 1) {
        unsigned v = 0, a = 0;
        if (tid < 256) { v = cs[tid]; a = (tid + off < 256) ? cs[tid + off] : 0u; }
        __syncthreads();
        if (tid < 256) cs[tid] = v + a;
        __syncthreads();
    }
    if (tid < 256) {
        unsigned sfx = cs[tid];
        unsigned nxt = (tid == 255) ? 0u : cs[tid + 1];
        if (sfx >= (unsigned)target && nxt < (unsigned)target) { s_chunk = tid; s_above1 = nxt; }
    }
    __syncthreads();

    int c = s_chunk;
    if (c < 0) {                 // fewer than 512 valid -> gather everything above thr
        if (tid == 0) d_T[b] = 1u;
        return;
    }
    int target2 = target - (int)s_above1;

    // suffix scan over the 256 bins of chunk c
    if (tid < 256) bs[tid] = H[c * 256 + tid];
    __syncthreads();
    #pragma unroll
    for (int off = 1; off < 256; off <<= 1) {
        unsigned v = 0, a = 0;
        if (tid < 256) { v = bs[tid]; a = (tid + off < 256) ? bs[tid + off] : 0u; }
        __syncthreads();
        if (tid < 256) bs[tid] = v + a;
        __syncthreads();
    }
    if (tid < 256) {
        unsigned sfx = bs[tid];
        unsigned nxt = (tid == 255) ? 0u : bs[tid + 1];
        if (sfx >= (unsigned)target2 && nxt < (unsigned)target2) s_bin = tid;
    }
    __syncthreads();

    if (tid == 0) {
        int bin = c * 256 + s_bin;
        // threshold = floor key of the crossing bin; bin 0 -> gather-all fallback
        d_T[b] = (bin == 0) ? 1u : (KEY_BASE + ((unsigned)bin << 7));
    }
}

// ---------------- K3: gather candidates with key >= T; also zero d_hist for next replay ----------
__global__ void gatherK(int N, int gx) {
    int b  = blockIdx.y;
    int q  = blockIdx.x * blockDim.x + threadIdx.x;
    int n0 = q * 4;

    // grid-stride zero of d_hist (runs AFTER selectTK read it; ready for next replay)
    {
        int flat = (b * gx + blockIdx.x) * blockDim.x + threadIdx.x;
        int total = gx * MAXB * blockDim.x;
        for (int i = flat; i < MAXB * NBIN; i += total) d_hist[i] = 0u;
    }

    if (n0 >= N) return;
    unsigned T = d_T[b];
    const float* S = d_score + (size_t)b * N;
    if (n0 + 3 < N) {
        float4 v = *(const float4*)(S + n0);
        float vv[4] = {v.x, v.y, v.z, v.w};
        #pragma unroll
        for (int k = 0; k < 4; k++) {
            if (vv[k] > SCORE_THR) {
                unsigned key = __float_as_uint(vv[k]);
                if (key >= T) {
                    int p = atomicAdd(&d_cnt[b], 1);
                    if (p < GCAP)
                        d_gath[b * GCAP + p] =
                            ((unsigned long long)key << 32) | (unsigned)(~(unsigned)(n0 + k));
                }
            }
        }
    } else {
        for (int k = 0; k < 4 && n0 + k < N; k++) {
            float s = S[n0 + k];
            if (s > SCORE_THR) {
                unsigned key = __float_as_uint(s);
                if (key >= T) {
                    int p = atomicAdd(&d_cnt[b], 1);
                    if (p < GCAP)
                        d_gath[b * GCAP + p] =
                            ((unsigned long long)key << 32) | (unsigned)(~(unsigned)(n0 + k));
                }
            }
        }
    }
}

// ---------------- K4: sort candidates, decode+clip boxes, NMS, write output ----------------
__global__ __launch_bounds__(1024, 1) void finalizeK(
    const float* __restrict__ anchors, const float* __restrict__ regs,
    const float* __restrict__ sizes, float* __restrict__ out, int N, int B)
{
    int b = blockIdx.x;
    int tid = threadIdx.x;

    __shared__ __align__(16) unsigned char sm[47296];
    unsigned int*       mask  = (unsigned int*)sm;            // [512][16]
    unsigned long long* arr   = (unsigned long long*)sm;      // [2048]
    float4*             sBox  = (float4*)(sm + 32768);
    float*              sArea = (float*) (sm + 40960);
    float*              sScore= (float*) (sm + 43008);
    int*                sLabel= (int*)   (sm + 45056);
    unsigned int*       keepW = (unsigned int*)(sm + 47104);
    int*                warpCnt = (int*)(sm + 47168);

    int cnt = d_cnt[b]; if (cnt > GCAP) cnt = GCAP;
    int nv  = cnt < KPRE ? cnt : KPRE;
    int S   = (cnt <= 512) ? 512 : ((cnt <= 1024) ? 1024 : 2048);

    for (int i = tid; i < S; i += blockDim.x)
        arr[i] = (i < cnt) ? d_gath[b * GCAP + i] : 0ull;
    __syncthreads();
    if (tid == 0) d_cnt[b] = 0;     // reset for next graph replay (after read)

    // bitonic sort, S elems descending (key desc, idx asc)
    for (int k = 2; k <= S; k <<= 1) {
        for (int j = k >> 1; j >= 1; j >>= 1) {
            if (tid < (S >> 1)) {
                int i = ((tid & ~(j - 1)) << 1) | (tid & (j - 1));
                int p = i + j;
                bool up = (i & k) != 0;
                unsigned long long a = arr[i], c2 = arr[p];
                bool sw = up ? (a > c2) : (a < c2);
                if (sw) { arr[i] = c2; arr[p] = a; }
            }
            __syncthreads();
        }
    }

    // decode + clip boxes for top nv; default-fill output with -1
    float H = sizes[b * 2 + 0], W = sizes[b * 2 + 1];
    if (tid < nv) {
        unsigned long long v = arr[tid];
        unsigned key = (unsigned)(v >> 32);
        int idx = (int)(~(unsigned)v);
        size_t off = (size_t)b * N + idx;
        float4 a = ((const float4*)anchors)[off];
        float4 r = ((const float4*)regs)[off];
        float w = a.z - a.x, h = a.w - a.y;
        float cx = a.x + 0.5f * w, cy = a.y + 0.5f * h;
        float dx = r.x * 0.1f, dy = r.y * 0.1f, dw = r.z * 0.2f, dh = r.w * 0.2f;
        float pcx = cx + dx * w, pcy = cy + dy * h;
        float pw = expf(dw) * w, ph = expf(dh) * h;
        float x1 = pcx - 0.5f * pw, y1 = pcy - 0.5f * ph;
        float x2 = pcx + 0.5f * pw, y2 = pcy + 0.5f * ph;
        x1 = fminf(fmaxf(x1, 0.f), W); x2 = fminf(fmaxf(x2, 0.f), W);
        y1 = fminf(fmaxf(y1, 0.f), H); y2 = fminf(fmaxf(y2, 0.f), H);
        sBox[tid]  = make_float4(x1, y1, x2, y2);
        sArea[tid] = (x2 - x1) * (y2 - y1);
        sScore[tid]= __uint_as_float(key);
        sLabel[tid]= d_label[off];
    }
    float* outB = out;
    float* outS = out + (size_t)B * MAXDET * 4;
    float* outL = out + (size_t)B * MAXDET * 5;
    if (tid < MAXDET) {
        ((float4*)outB)[b * MAXDET + tid] = make_float4(-1.f, -1.f, -1.f, -1.f);
        outS[b * MAXDET + tid] = -1.f;
        outL[b * MAXDET + tid] = -1.f;
    }
    __syncthreads();   // arr reads done -> mask may now overwrite that region

    // parallel IoU suppression bitmask (division-free)
    if (tid < KPRE) {
        float4 bi; float ai = 0.f;
        bool v = tid < nv;
        if (v) { bi = sBox[tid]; ai = sArea[tid]; }
        for (int w = 0; w < 16; w++) {
            unsigned word = 0;
            if (v) {
                int j0 = w * 32, j1 = j0 + 32;
                if (j1 > nv) j1 = nv;
                int js = (tid + 1 > j0) ? tid + 1 : j0;
                for (int j = js; j < j1; j++) {
                    float4 bj = sBox[j];
                    float lx = fmaxf(bi.x, bj.x), ly = fmaxf(bi.y, bj.y);
                    float rx = fminf(bi.z, bj.z), ry = fminf(bi.w, bj.w);
                    float iw = fmaxf(rx - lx, 0.f), ih = fmaxf(ry - ly, 0.f);
                    float inter = iw * ih;
                    float lhs = inter * (1.0f + IOU_THR);
                    float rhs = IOU_THR * (ai + sArea[j] + 1e-9f);
                    if (lhs > rhs) word |= 1u << (j & 31);
                }
            }
            mask[tid * 16 + w] = word;
        }
    }
    __syncthreads();

    // warp-serial greedy resolution; iterate only KEPT candidates via ffs
    if (tid < 32) {
        unsigned kw = 0;
        if (tid < 16) {
            int full = nv >> 5, rem = nv & 31;
            kw = (tid < full) ? 0xFFFFFFFFu
               : ((tid == full && rem) ? ((1u << rem) - 1u) : 0u);
        }
        for (int g = 0; g < 16; g++) {
            unsigned ow = __shfl_sync(0xFFFFFFFFu, kw, g);
            while (ow) {
                int bit = __ffs(ow) - 1;
                int i = g * 32 + bit;
                if (tid < 16) kw &= ~mask[i * 16 + tid];
                ow = __shfl_sync(0xFFFFFFFFu, kw, g);
                ow &= (bit == 31) ? 0u : ~((2u << bit) - 1u);
            }
        }
        if (tid < 16) keepW[tid] = kw;
    }
    __syncthreads();

    // compact kept candidates (score order) into first <=300 slots
    bool kept = false;
    if (tid < nv) kept = (keepW[tid >> 5] >> (tid & 31)) & 1u;
    unsigned wm = __ballot_sync(0xFFFFFFFFu, kept);
    int w = tid >> 5, lane = tid & 31;
    if (lane == 0) warpCnt[w] = __popc(wm);
    __syncthreads();
    if (kept) {
        int prefix = 0;
        for (int i = 0; i < w; i++) prefix += warpCnt[i];
        int pos = prefix + __popc(wm & ((1u << lane) - 1u));
        if (pos < MAXDET) {
            ((float4*)outB)[b * MAXDET + pos] = sBox[tid];
            outS[b * MAXDET + pos] = sScore[tid];
            outL[b * MAXDET + pos] = (float)sLabel[tid];
        }
    }
}

// ---------------- launch ----------------
extern "C" void kernel_launch(void* const* d_in, const int* in_sizes, int n_in,
                              void* d_out, int out_size) {
    const float* anchors = (const float*)d_in[0];
    const float* regs    = (const float*)d_in[1];
    const float* cls     = (const float*)d_in[2];
    const float* sizes   = (const float*)d_in[3];

    int B = in_sizes[3] / 2;            // sizes is [B,2]
    if (B <= 0 || B > MAXB) B = MAXB;
    int N = in_sizes[0] / (B * 4);      // anchors [B,N,4]
    long long clsElems = (long long)in_sizes[2];
    int C = (int)(clsElems / ((long long)B * N));

    int N4 = (N + 3) / 4;
    int gx = (N4 + 255) / 256;
    dim3 gridV(gx, B);

    if (C == 80) {
        dim3 gridS(((N * 4) + 255) / 256, B);
        scoreK80<<<gridS, 256>>>(cls, N);
    } else {
        dim3 gridBN((N + 255) / 256, B);
        scoreKgen<<<gridBN, 256>>>(cls, N, C);
    }
    selectTK<<<B, 1024>>>();
    gatherK<<<gridV, 256>>>(N, gx);
    finalizeK<<<B, 1024>>>(anchors, regs, sizes, (float*)d_out, N, B);
}